// round 2
// baseline (speedup 1.0000x reference)
#include <cuda_runtime.h>
#include <math.h>

#define JN 4096
#define CN 8192
#define JC ((size_t)JN * (size_t)CN)

// ---------------- device scratch (no allocations allowed) ----------------
__device__ int   g_rank[JN];
__device__ float g_hs[JN], g_Ls[JN];
__device__ float g_row[JN], g_colJ[JN], g_norm[JN];
__device__ float g_w1[3][JN];
__device__ float g_w2[3][JN];
__device__ float g_pp[32][3][JN];     // deterministic prop partials
__device__ float g_U[JN][8];
__device__ float g_V[8][CN];
__device__ float g_bias[CN];
#define NPART 512
__device__ float g_pm[NPART], g_ps[NPART];
__device__ float g_gm, g_gs;

__device__ __forceinline__ float neg_inf() { return __int_as_float(0xff800000); }

__device__ __forceinline__ float4 f4fma(float a, float4 b, float4 c) {
    c.x = fmaf(a, b.x, c.x); c.y = fmaf(a, b.y, c.y);
    c.z = fmaf(a, b.z, c.z); c.w = fmaf(a, b.w, c.w);
    return c;
}

__device__ __forceinline__ void smupd(float& m, float& s, float t) {
    if (t > m) { s = s * __expf(m - t) + 1.f; m = t; }
    else { float d = t - m; if (d > -100.f) s += __expf(d); }
}

// combine two (m,s) softmax partials
__device__ __forceinline__ void smcomb(float& m, float& s, float om, float os) {
    float nm = fmaxf(m, om);
    s = s * __expf(m - nm) + os * __expf(om - nm);
    m = nm;
}

// ---------------- kernels ----------------

__global__ void k_init() {
    int i = blockIdx.x * blockDim.x + threadIdx.x;
    if (i < JN) {
        g_rank[i] = 0;
        g_row[i] = 0.f; g_colJ[i] = 0.f;
    }
}

// rank[i] = #{j : h[j] > h[i]} + #{j : h[j]==h[i] && j<i}  (== position in argsort(-h))
__global__ void k_rank(const float* __restrict__ h) {
    __shared__ float sh[256];
    int t = threadIdx.x;
    int i = blockIdx.x * 256 + t;
    float hi = h[i];
    int jbase = blockIdx.y * 256;
    sh[t] = h[jbase + t];
    __syncthreads();
    int cnt = 0;
    #pragma unroll 8
    for (int k = 0; k < 256; k++) {
        float hj = sh[k];
        int j = jbase + k;
        cnt += (hj > hi) || (hj == hi && j < i);
    }
    atomicAdd(&g_rank[i], cnt);
}

__global__ void k_scatter(const float* __restrict__ h, const float* __restrict__ L) {
    int i = blockIdx.x * 256 + threadIdx.x;
    int r = g_rank[i];
    g_hs[r] = h[i];
    g_Ls[r] = L[i];
}

// full-Graph pass: row sums (all C cols) + col sums for c < JN
// (sums of 0/1 values are exact integers -> float atomics are order-invariant)
__global__ void k_sums(const float* __restrict__ G) {
    __shared__ float srow[128];
    int t = threadIdx.x;
    int c = blockIdx.x * 256 + t;
    int j0 = blockIdx.y * 128;
    if (t < 128) srow[t] = 0.f;
    __syncthreads();
    float colacc = 0.f;
    const float* gp = G + (size_t)j0 * CN + c;
    for (int r = 0; r < 128; r++) {
        float v = gp[(size_t)r * CN];
        colacc += v;
        #pragma unroll
        for (int off = 16; off; off >>= 1) v += __shfl_xor_sync(0xffffffffu, v, off);
        if ((t & 31) == 0) atomicAdd(&srow[r], v);
    }
    __syncthreads();
    if (t < 128) atomicAdd(&g_row[j0 + t], srow[t]);
    if (c < JN) atomicAdd(&g_colJ[c], colacc);
}

__global__ void k_fin1() {
    int i = blockIdx.x * 256 + threadIdx.x;
    float n = rsqrtf(fmaxf(g_colJ[i], 1.f));
    g_norm[i] = n;
    g_w1[0][i] = n * g_hs[i];
    g_w1[1][i] = n * g_Ls[i];
    g_w1[2][i] = n;
}

// partial[by][q][c] = sum_{j in chunk by} G[j,c] * w[q][j]   over left JN x JN block
template <int PASS>
__global__ void k_prop(const float* __restrict__ G) {
    const float* w0 = PASS ? g_w2[0] : g_w1[0];
    const float* w1 = PASS ? g_w2[1] : g_w1[1];
    const float* w2 = PASS ? g_w2[2] : g_w1[2];
    __shared__ float s0[128], s1[128], s2[128];
    int t = threadIdx.x;
    int c = blockIdx.x * 256 + t;     // c < JN
    int j0 = blockIdx.y * 128;
    if (t < 128) { s0[t] = w0[j0 + t]; s1[t] = w1[j0 + t]; s2[t] = w2[j0 + t]; }
    __syncthreads();
    float a = 0.f, b = 0.f, s = 0.f;
    const float* gp = G + (size_t)j0 * CN + c;
    #pragma unroll 8
    for (int r = 0; r < 128; r++) {
        float v = gp[(size_t)r * CN];
        a = fmaf(v, s0[r], a);
        b = fmaf(v, s1[r], b);
        s = fmaf(v, s2[r], s);
    }
    g_pp[blockIdx.y][0][c] = a;
    g_pp[blockIdx.y][1][c] = b;
    g_pp[blockIdx.y][2][c] = s;
}

__global__ void k_fin2() {
    int i = blockIdx.x * 256 + threadIdx.x;
    float n = g_norm[i];
    float a = 0.f, b = 0.f, s = 0.f;
    #pragma unroll
    for (int p = 0; p < 32; p++) {
        a += g_pp[p][0][i];
        b += g_pp[p][1][i];
        s += g_pp[p][2][i];
    }
    float a1 = n * a, b1 = n * b, s1 = n * s;
    g_U[i][0] = g_hs[i];
    g_U[i][1] = g_Ls[i];
    g_U[i][2] = a1;
    g_U[i][3] = b1;
    g_U[i][4] = s1;
    g_w2[0][i] = n * a1;
    g_w2[1][i] = n * b1;
    g_w2[2][i] = n * s1;
}

__global__ void k_fin3() {
    int i = blockIdx.x * 256 + threadIdx.x;
    float n = g_norm[i];
    float a = 0.f, b = 0.f, s = 0.f;
    #pragma unroll
    for (int p = 0; p < 32; p++) {
        a += g_pp[p][0][i];
        b += g_pp[p][1][i];
        s += g_pp[p][2][i];
    }
    g_U[i][5] = n * a;
    g_U[i][6] = n * b;
    g_U[i][7] = n * s;
}

// V[8][CN], bias[CN] from tag_w(18x64)@lin_w(64xCN), tag_b, lin_b, scalars W,P,N
__global__ void k_vmat(const float* __restrict__ tag_w, const float* __restrict__ tag_b,
                       const float* __restrict__ lin_w, const float* __restrict__ lin_b,
                       const float* __restrict__ Wp, const float* __restrict__ Pp,
                       const float* __restrict__ Np) {
    __shared__ float stw[18 * 64];
    __shared__ float stb[64];
    int t = threadIdx.x;
    for (int k = t; k < 18 * 64; k += 256) stw[k] = tag_w[k];
    if (t < 64) stb[t] = tag_b[t];
    __syncthreads();
    int c = blockIdx.x * 256 + t;
    float m[18];
    #pragma unroll
    for (int q = 0; q < 18; q++) m[q] = 0.f;
    float tb = 0.f;
    for (int k = 0; k < 64; k++) {
        float lw = lin_w[(size_t)k * CN + c];
        #pragma unroll
        for (int q = 0; q < 18; q++) m[q] = fmaf(stw[q * 64 + k], lw, m[q]);
        tb = fmaf(stb[k], lw, tb);
    }
    float Wv = *Wp, Pv = *Pp, Nv = *Np;
    g_V[0][c] = m[0];
    g_V[1][c] = m[1];
    g_V[2][c] = m[6];
    g_V[3][c] = m[7];
    g_V[4][c] = Wv * m[8] + Pv * m[9] + Nv * m[10] + m[11];
    g_V[5][c] = m[12];
    g_V[6][c] = m[13];
    g_V[7][c] = Wv * m[14] + Pv * m[15] + Nv * m[16] + m[17];
    g_bias[c] = lin_b[c] + tb + Wv * m[2] + Pv * m[3] + Nv * m[4] + m[5];
}

#define VROWS 64
// Value = U @ V + bias; write Value; fused online-softmax stats on tmp = Value - pen
__global__ void k_value(float* __restrict__ Value) {
    __shared__ float4 sU2[VROWS][2];
    __shared__ float srw[VROWS], scl[VROWS];
    __shared__ float red_m[8], red_s[8];
    int t = threadIdx.x;
    int c0 = blockIdx.x * 1024 + t * 4;
    int i0 = blockIdx.y * VROWS;
    for (int k = t; k < VROWS * 2; k += 256)
        sU2[k >> 1][k & 1] = ((const float4*)g_U)[i0 * 2 + k];
    if (t < VROWS) { srw[t] = g_row[i0 + t]; scl[t] = g_colJ[i0 + t]; }
    __syncthreads();
    float4 V[8];
    #pragma unroll
    for (int q = 0; q < 8; q++) V[q] = *(const float4*)&g_V[q][c0];
    float4 bs = *(const float4*)&g_bias[c0];
    bool leftblk = (c0 < JN);
    float4 rowc = make_float4(0, 0, 0, 0), colc = make_float4(0, 0, 0, 0);
    if (leftblk) { rowc = *(const float4*)&g_row[c0]; colc = *(const float4*)&g_colJ[c0]; }
    float m = neg_inf(), s = 0.f;
    for (int r = 0; r < VROWS; r++) {
        int i = i0 + r;
        float4 u0 = sU2[r][0], u1 = sU2[r][1];
        float4 val = bs;
        val = f4fma(u0.x, V[0], val);
        val = f4fma(u0.y, V[1], val);
        val = f4fma(u0.z, V[2], val);
        val = f4fma(u0.w, V[3], val);
        val = f4fma(u1.x, V[4], val);
        val = f4fma(u1.y, V[5], val);
        val = f4fma(u1.z, V[6], val);
        val = f4fma(u1.w, V[7], val);
        *(float4*)&Value[(size_t)i * CN + c0] = val;
        float ri = srw[r], cli = scl[r];
        if (!leftblk) {
            float pen = ri * 10000.f;
            smupd(m, s, val.x - pen);
            smupd(m, s, val.y - pen);
            smupd(m, s, val.z - pen);
            smupd(m, s, val.w - pen);
        } else {
            float base = ri + cli;
            float px = ((c0 + 0) > i && base + rowc.x + colc.x == 0.f) ? 0.f : 10000.f;
            float py = ((c0 + 1) > i && base + rowc.y + colc.y == 0.f) ? 0.f : 10000.f;
            float pz = ((c0 + 2) > i && base + rowc.z + colc.z == 0.f) ? 0.f : 10000.f;
            float pw = ((c0 + 3) > i && base + rowc.w + colc.w == 0.f) ? 0.f : 10000.f;
            smupd(m, s, val.x - px);
            smupd(m, s, val.y - py);
            smupd(m, s, val.z - pz);
            smupd(m, s, val.w - pw);
        }
    }
    #pragma unroll
    for (int off = 16; off; off >>= 1) {
        float om = __shfl_xor_sync(0xffffffffu, m, off);
        float os = __shfl_xor_sync(0xffffffffu, s, off);
        smcomb(m, s, om, os);
    }
    if ((t & 31) == 0) { red_m[t >> 5] = m; red_s[t >> 5] = s; }
    __syncthreads();
    if (t == 0) {
        float M = red_m[0], S = red_s[0];
        for (int k = 1; k < 8; k++) smcomb(M, S, red_m[k], red_s[k]);
        int pid = blockIdx.y * gridDim.x + blockIdx.x;
        g_pm[pid] = M; g_ps[pid] = S;
    }
}

__global__ void k_gred() {
    __shared__ float rm[256], rs[256];
    int t = threadIdx.x;
    float m = neg_inf(), s = 0.f;
    for (int k = t; k < NPART; k += 256) smcomb(m, s, g_pm[k], g_ps[k]);
    rm[t] = m; rs[t] = s;
    __syncthreads();
    for (int w = 128; w; w >>= 1) {
        if (t < w) {
            float om = rm[t + w], os = rs[t + w];
            float mm = rm[t], ss = rs[t];
            smcomb(mm, ss, om, os);
            rm[t] = mm; rs[t] = ss;
        }
        __syncthreads();
    }
    if (t == 0) { g_gm = rm[0]; g_gs = rs[0]; }
}

// recompute Value (rank-8, cheaper than re-reading 128MB), write Poss
__global__ void k_poss(float* __restrict__ Poss) {
    __shared__ float4 sU2[VROWS][2];
    __shared__ float srw[VROWS], scl[VROWS];
    int t = threadIdx.x;
    int c0 = blockIdx.x * 1024 + t * 4;
    int i0 = blockIdx.y * VROWS;
    for (int k = t; k < VROWS * 2; k += 256)
        sU2[k >> 1][k & 1] = ((const float4*)g_U)[i0 * 2 + k];
    if (t < VROWS) { srw[t] = g_row[i0 + t]; scl[t] = g_colJ[i0 + t]; }
    __syncthreads();
    float4 V[8];
    #pragma unroll
    for (int q = 0; q < 8; q++) V[q] = *(const float4*)&g_V[q][c0];
    float4 bs = *(const float4*)&g_bias[c0];
    bool leftblk = (c0 < JN);
    float4 rowc = make_float4(0, 0, 0, 0), colc = make_float4(0, 0, 0, 0);
    if (leftblk) { rowc = *(const float4*)&g_row[c0]; colc = *(const float4*)&g_colJ[c0]; }
    float gm = g_gm;
    float rgs = 1.f / g_gs;
    for (int r = 0; r < VROWS; r++) {
        int i = i0 + r;
        float4 u0 = sU2[r][0], u1 = sU2[r][1];
        float4 val = bs;
        val = f4fma(u0.x, V[0], val);
        val = f4fma(u0.y, V[1], val);
        val = f4fma(u0.z, V[2], val);
        val = f4fma(u0.w, V[3], val);
        val = f4fma(u1.x, V[4], val);
        val = f4fma(u1.y, V[5], val);
        val = f4fma(u1.z, V[6], val);
        val = f4fma(u1.w, V[7], val);
        float ri = srw[r], cli = scl[r];
        float4 d;
        if (!leftblk) {
            float pen = ri * 10000.f + gm;
            d = make_float4(val.x - pen, val.y - pen, val.z - pen, val.w - pen);
        } else {
            float base = ri + cli;
            float px = ((c0 + 0) > i && base + rowc.x + colc.x == 0.f) ? 0.f : 10000.f;
            float py = ((c0 + 1) > i && base + rowc.y + colc.y == 0.f) ? 0.f : 10000.f;
            float pz = ((c0 + 2) > i && base + rowc.z + colc.z == 0.f) ? 0.f : 10000.f;
            float pw = ((c0 + 3) > i && base + rowc.w + colc.w == 0.f) ? 0.f : 10000.f;
            d = make_float4(val.x - px - gm, val.y - py - gm,
                            val.z - pz - gm, val.w - pw - gm);
        }
        float4 p;
        p.x = (d.x > -100.f) ? __expf(d.x) * rgs : 0.f;
        p.y = (d.y > -100.f) ? __expf(d.y) * rgs : 0.f;
        p.z = (d.z > -100.f) ? __expf(d.z) * rgs : 0.f;
        p.w = (d.w > -100.f) ? __expf(d.w) * rgs : 0.f;
        *(float4*)&Poss[(size_t)i * CN + c0] = p;
    }
}

// ---------------- launch ----------------
extern "C" void kernel_launch(void* const* d_in, const int* in_sizes, int n_in,
                              void* d_out, int out_size) {
    const float* h     = (const float*)d_in[0];
    const float* L     = (const float*)d_in[1];
    const float* Wp    = (const float*)d_in[2];
    const float* Pp    = (const float*)d_in[3];
    const float* Np    = (const float*)d_in[4];
    const float* G     = (const float*)d_in[5];
    const float* tag_w = (const float*)d_in[6];
    const float* tag_b = (const float*)d_in[7];
    const float* lin_w = (const float*)d_in[8];
    const float* lin_b = (const float*)d_in[9];
    float* Value = (float*)d_out;
    float* Poss  = Value + JC;

    k_init<<<16, 256>>>();
    k_rank<<<dim3(16, 16), 256>>>(h);
    k_scatter<<<16, 256>>>(h, L);
    k_sums<<<dim3(32, 32), 256>>>(G);
    k_fin1<<<16, 256>>>();
    k_prop<0><<<dim3(16, 32), 256>>>(G);
    k_fin2<<<16, 256>>>();
    k_prop<1><<<dim3(16, 32), 256>>>(G);
    k_fin3<<<16, 256>>>();
    k_vmat<<<32, 256>>>(tag_w, tag_b, lin_w, lin_b, Wp, Pp, Np);
    k_value<<<dim3(8, 64), 256>>>(Value);
    k_gred<<<1, 256>>>();
    k_poss<<<dim3(8, 64), 256>>>(Poss);
}

// round 3
// speedup vs baseline: 1.0569x; 1.0569x over previous
#include <cuda_runtime.h>
#include <math.h>

#define JN 4096
#define CN 8192
#define JC ((size_t)JN * (size_t)CN)
#define JW (JN / 32)          // 128 words per row of packed left-graph

// ---------------- device scratch (no allocations allowed) ----------------
__device__ int      g_rank[JN];
__device__ float    g_hs[JN], g_Ls[JN];
__device__ float    g_row[JN], g_colJ[JN], g_norm[JN];
__device__ unsigned g_bits[JN][JW];   // packed left J x J graph (2MB)
__device__ float    g_w1[3][JN];
__device__ float    g_w2[3][JN];
__device__ float    g_pp[32][3][JN];  // deterministic prop partials
__device__ float    g_U[JN][8];
__device__ float    g_V[8][CN];
__device__ float    g_bias[CN];
#define NPART 512
__device__ float g_pm[NPART], g_ps[NPART];
__device__ float g_gm, g_gs;

__device__ __forceinline__ float neg_inf() { return __int_as_float(0xff800000); }

__device__ __forceinline__ float4 f4fma(float a, float4 b, float4 c) {
    c.x = fmaf(a, b.x, c.x); c.y = fmaf(a, b.y, c.y);
    c.z = fmaf(a, b.z, c.z); c.w = fmaf(a, b.w, c.w);
    return c;
}

__device__ __forceinline__ void smupd(float& m, float& s, float t) {
    if (t > m) { s = s * __expf(m - t) + 1.f; m = t; }
    else { float d = t - m; if (d > -100.f) s += __expf(d); }
}

__device__ __forceinline__ void smcomb(float& m, float& s, float om, float os) {
    float nm = fmaxf(m, om);
    s = s * __expf(m - nm) + os * __expf(om - nm);
    m = nm;
}

// ---------------- kernels ----------------

__global__ void k_init() {
    int i = blockIdx.x * blockDim.x + threadIdx.x;
    if (i < JN) {
        g_rank[i] = 0;
        g_row[i] = 0.f; g_colJ[i] = 0.f;
    }
}

// rank[i] = #{j : h[j] > h[i]} + #{j : h[j]==h[i] && j<i}
__global__ void k_rank(const float* __restrict__ h) {
    __shared__ float sh[256];
    int t = threadIdx.x;
    int i = blockIdx.x * 256 + t;
    float hi = h[i];
    int jbase = blockIdx.y * 256;
    sh[t] = h[jbase + t];
    __syncthreads();
    int cnt = 0;
    #pragma unroll 8
    for (int k = 0; k < 256; k++) {
        float hj = sh[k];
        int j = jbase + k;
        cnt += (hj > hi) || (hj == hi && j < i);
    }
    atomicAdd(&g_rank[i], cnt);
}

__global__ void k_scatter(const float* __restrict__ h, const float* __restrict__ L) {
    int i = blockIdx.x * 256 + threadIdx.x;
    int r = g_rank[i];
    g_hs[r] = h[i];
    g_Ls[r] = L[i];
}

// Full-Graph pass: row sums (all C cols) via ballot+popc, col sums for c < JN,
// and packs the left J x J half into g_bits for the prop passes.
// All accumulated values are exact small integers -> float atomics order-invariant.
__global__ void k_sums(const float* __restrict__ G) {
    int t = threadIdx.x;
    int lane = t & 31;
    int wi = t >> 5;                       // warp id in block (0..7)
    int c0 = blockIdx.x * 256;             // column window base
    int c = c0 + t;
    int j0 = blockIdx.y * 128;             // row chunk base
    bool left = (c0 < JN);

    int rowacc[4] = {0, 0, 0, 0};
    float colacc = 0.f;
    const float* gp = G + (size_t)j0 * CN + c;
    unsigned* bitp = left ? &g_bits[j0][(c0 >> 5) + wi] : 0;

    #pragma unroll 4
    for (int r = 0; r < 128; r++) {
        float v = gp[(size_t)r * CN];
        unsigned b = __ballot_sync(0xffffffffu, v != 0.f);
        int pc = __popc(b);
        if (lane == (r & 31)) rowacc[r >> 5] += pc;
        if (left) {
            colacc += v;
            if (lane == 0) bitp[(size_t)r * JW] = b;
        }
    }
    #pragma unroll
    for (int q = 0; q < 4; q++)
        atomicAdd(&g_row[j0 + q * 32 + lane], (float)rowacc[q]);
    if (left) atomicAdd(&g_colJ[c], colacc);
}

__global__ void k_fin1() {
    int i = blockIdx.x * 256 + threadIdx.x;
    float n = rsqrtf(fmaxf(g_colJ[i], 1.f));
    g_norm[i] = n;
    g_w1[0][i] = n * g_hs[i];
    g_w1[1][i] = n * g_Ls[i];
    g_w1[2][i] = n;
}

// Bit-graph prop: partial[by][q][c] = sum_{j in chunk} bit(j,c) * w[q][j]
// Block: 1024 columns (bx*1024), 128-row chunk (by*128). 256 threads, 4 cols each.
template <int PASS>
__global__ void k_prop() {
    const float* w0 = PASS ? g_w2[0] : g_w1[0];
    const float* w1 = PASS ? g_w2[1] : g_w1[1];
    const float* w2 = PASS ? g_w2[2] : g_w1[2];
    __shared__ unsigned sw[128][32];   // 128 rows x 32 words (1024 cols)
    __shared__ float s0[128], s1[128], s2[128];
    int t = threadIdx.x;
    int c0 = blockIdx.x * 1024;
    int j0 = blockIdx.y * 128;

    for (int idx = t; idx < 128 * 32; idx += 256) {
        int row = idx >> 5, w = idx & 31;
        sw[row][w] = g_bits[j0 + row][(c0 >> 5) + w];
    }
    if (t < 128) {
        s0[t] = w0[j0 + t]; s1[t] = w1[j0 + t]; s2[t] = w2[j0 + t];
    }
    __syncthreads();

    int wslot = t >> 3;            // which of 32 words this thread reads
    int bsh = (t & 7) * 4;         // bit offset of this thread's 4 columns
    float a0x=0,a0y=0,a0z=0,a0w=0;
    float a1x=0,a1y=0,a1z=0,a1w=0;
    float a2x=0,a2y=0,a2z=0,a2w=0;
    #pragma unroll 4
    for (int r = 0; r < 128; r++) {
        unsigned wd = sw[r][wslot] >> bsh;
        float u0 = s0[r], u1 = s1[r], u2 = s2[r];
        if (wd & 1u) { a0x += u0; a1x += u1; a2x += u2; }
        if (wd & 2u) { a0y += u0; a1y += u1; a2y += u2; }
        if (wd & 4u) { a0z += u0; a1z += u1; a2z += u2; }
        if (wd & 8u) { a0w += u0; a1w += u1; a2w += u2; }
    }
    int c = c0 + t * 4;
    *(float4*)&g_pp[blockIdx.y][0][c] = make_float4(a0x, a0y, a0z, a0w);
    *(float4*)&g_pp[blockIdx.y][1][c] = make_float4(a1x, a1y, a1z, a1w);
    *(float4*)&g_pp[blockIdx.y][2][c] = make_float4(a2x, a2y, a2z, a2w);
}

__global__ void k_fin2() {
    int i = blockIdx.x * 256 + threadIdx.x;
    float n = g_norm[i];
    float a = 0.f, b = 0.f, s = 0.f;
    #pragma unroll
    for (int p = 0; p < 32; p++) {
        a += g_pp[p][0][i];
        b += g_pp[p][1][i];
        s += g_pp[p][2][i];
    }
    float a1 = n * a, b1 = n * b, s1 = n * s;
    g_U[i][0] = g_hs[i];
    g_U[i][1] = g_Ls[i];
    g_U[i][2] = a1;
    g_U[i][3] = b1;
    g_U[i][4] = s1;
    g_w2[0][i] = n * a1;
    g_w2[1][i] = n * b1;
    g_w2[2][i] = n * s1;
}

__global__ void k_fin3() {
    int i = blockIdx.x * 256 + threadIdx.x;
    float n = g_norm[i];
    float a = 0.f, b = 0.f, s = 0.f;
    #pragma unroll
    for (int p = 0; p < 32; p++) {
        a += g_pp[p][0][i];
        b += g_pp[p][1][i];
        s += g_pp[p][2][i];
    }
    g_U[i][5] = n * a;
    g_U[i][6] = n * b;
    g_U[i][7] = n * s;
}

// V[8][CN], bias[CN] from tag_w(18x64)@lin_w(64xCN), tag_b, lin_b, scalars W,P,N
__global__ void k_vmat(const float* __restrict__ tag_w, const float* __restrict__ tag_b,
                       const float* __restrict__ lin_w, const float* __restrict__ lin_b,
                       const float* __restrict__ Wp, const float* __restrict__ Pp,
                       const float* __restrict__ Np) {
    __shared__ float stw[18 * 64];
    __shared__ float stb[64];
    int t = threadIdx.x;
    for (int k = t; k < 18 * 64; k += 256) stw[k] = tag_w[k];
    if (t < 64) stb[t] = tag_b[t];
    __syncthreads();
    int c = blockIdx.x * 256 + t;
    float m[18];
    #pragma unroll
    for (int q = 0; q < 18; q++) m[q] = 0.f;
    float tb = 0.f;
    for (int k = 0; k < 64; k++) {
        float lw = lin_w[(size_t)k * CN + c];
        #pragma unroll
        for (int q = 0; q < 18; q++) m[q] = fmaf(stw[q * 64 + k], lw, m[q]);
        tb = fmaf(stb[k], lw, tb);
    }
    float Wv = *Wp, Pv = *Pp, Nv = *Np;
    g_V[0][c] = m[0];
    g_V[1][c] = m[1];
    g_V[2][c] = m[6];
    g_V[3][c] = m[7];
    g_V[4][c] = Wv * m[8] + Pv * m[9] + Nv * m[10] + m[11];
    g_V[5][c] = m[12];
    g_V[6][c] = m[13];
    g_V[7][c] = Wv * m[14] + Pv * m[15] + Nv * m[16] + m[17];
    g_bias[c] = lin_b[c] + tb + Wv * m[2] + Pv * m[3] + Nv * m[4] + m[5];
}

#define VROWS 64
// Value = U @ V + bias; write Value; fused online-softmax stats on tmp = Value - pen
__global__ void k_value(float* __restrict__ Value) {
    __shared__ float4 sU2[VROWS][2];
    __shared__ float srw[VROWS], scl[VROWS];
    __shared__ float red_m[8], red_s[8];
    int t = threadIdx.x;
    int c0 = blockIdx.x * 1024 + t * 4;
    int i0 = blockIdx.y * VROWS;
    for (int k = t; k < VROWS * 2; k += 256)
        sU2[k >> 1][k & 1] = ((const float4*)g_U)[i0 * 2 + k];
    if (t < VROWS) { srw[t] = g_row[i0 + t]; scl[t] = g_colJ[i0 + t]; }
    __syncthreads();
    float4 V[8];
    #pragma unroll
    for (int q = 0; q < 8; q++) V[q] = *(const float4*)&g_V[q][c0];
    float4 bs = *(const float4*)&g_bias[c0];
    bool leftblk = (c0 < JN);
    float4 rowc = make_float4(0, 0, 0, 0), colc = make_float4(0, 0, 0, 0);
    if (leftblk) { rowc = *(const float4*)&g_row[c0]; colc = *(const float4*)&g_colJ[c0]; }
    float m = neg_inf(), s = 0.f;
    for (int r = 0; r < VROWS; r++) {
        int i = i0 + r;
        float4 u0 = sU2[r][0], u1 = sU2[r][1];
        float4 val = bs;
        val = f4fma(u0.x, V[0], val);
        val = f4fma(u0.y, V[1], val);
        val = f4fma(u0.z, V[2], val);
        val = f4fma(u0.w, V[3], val);
        val = f4fma(u1.x, V[4], val);
        val = f4fma(u1.y, V[5], val);
        val = f4fma(u1.z, V[6], val);
        val = f4fma(u1.w, V[7], val);
        *(float4*)&Value[(size_t)i * CN + c0] = val;
        float ri = srw[r], cli = scl[r];
        if (!leftblk) {
            float pen = ri * 10000.f;
            smupd(m, s, val.x - pen);
            smupd(m, s, val.y - pen);
            smupd(m, s, val.z - pen);
            smupd(m, s, val.w - pen);
        } else {
            float base = ri + cli;
            float px = ((c0 + 0) > i && base + rowc.x + colc.x == 0.f) ? 0.f : 10000.f;
            float py = ((c0 + 1) > i && base + rowc.y + colc.y == 0.f) ? 0.f : 10000.f;
            float pz = ((c0 + 2) > i && base + rowc.z + colc.z == 0.f) ? 0.f : 10000.f;
            float pw = ((c0 + 3) > i && base + rowc.w + colc.w == 0.f) ? 0.f : 10000.f;
            smupd(m, s, val.x - px);
            smupd(m, s, val.y - py);
            smupd(m, s, val.z - pz);
            smupd(m, s, val.w - pw);
        }
    }
    #pragma unroll
    for (int off = 16; off; off >>= 1) {
        float om = __shfl_xor_sync(0xffffffffu, m, off);
        float os = __shfl_xor_sync(0xffffffffu, s, off);
        smcomb(m, s, om, os);
    }
    if ((t & 31) == 0) { red_m[t >> 5] = m; red_s[t >> 5] = s; }
    __syncthreads();
    if (t == 0) {
        float M = red_m[0], S = red_s[0];
        for (int k = 1; k < 8; k++) smcomb(M, S, red_m[k], red_s[k]);
        int pid = blockIdx.y * gridDim.x + blockIdx.x;
        g_pm[pid] = M; g_ps[pid] = S;
    }
}

__global__ void k_gred() {
    __shared__ float rm[256], rs[256];
    int t = threadIdx.x;
    float m = neg_inf(), s = 0.f;
    for (int k = t; k < NPART; k += 256) smcomb(m, s, g_pm[k], g_ps[k]);
    rm[t] = m; rs[t] = s;
    __syncthreads();
    for (int w = 128; w; w >>= 1) {
        if (t < w) {
            float om = rm[t + w], os = rs[t + w];
            float mm = rm[t], ss = rs[t];
            smcomb(mm, ss, om, os);
            rm[t] = mm; rs[t] = ss;
        }
        __syncthreads();
    }
    if (t == 0) { g_gm = rm[0]; g_gs = rs[0]; }
}

// recompute Value (rank-8, cheaper than re-reading 128MB), write Poss
__global__ void k_poss(float* __restrict__ Poss) {
    __shared__ float4 sU2[VROWS][2];
    __shared__ float srw[VROWS], scl[VROWS];
    int t = threadIdx.x;
    int c0 = blockIdx.x * 1024 + t * 4;
    int i0 = blockIdx.y * VROWS;
    for (int k = t; k < VROWS * 2; k += 256)
        sU2[k >> 1][k & 1] = ((const float4*)g_U)[i0 * 2 + k];
    if (t < VROWS) { srw[t] = g_row[i0 + t]; scl[t] = g_colJ[i0 + t]; }
    __syncthreads();
    float4 V[8];
    #pragma unroll
    for (int q = 0; q < 8; q++) V[q] = *(const float4*)&g_V[q][c0];
    float4 bs = *(const float4*)&g_bias[c0];
    bool leftblk = (c0 < JN);
    float4 rowc = make_float4(0, 0, 0, 0), colc = make_float4(0, 0, 0, 0);
    if (leftblk) { rowc = *(const float4*)&g_row[c0]; colc = *(const float4*)&g_colJ[c0]; }
    float gm = g_gm;
    float rgs = 1.f / g_gs;
    for (int r = 0; r < VROWS; r++) {
        int i = i0 + r;
        float4 u0 = sU2[r][0], u1 = sU2[r][1];
        float4 val = bs;
        val = f4fma(u0.x, V[0], val);
        val = f4fma(u0.y, V[1], val);
        val = f4fma(u0.z, V[2], val);
        val = f4fma(u0.w, V[3], val);
        val = f4fma(u1.x, V[4], val);
        val = f4fma(u1.y, V[5], val);
        val = f4fma(u1.z, V[6], val);
        val = f4fma(u1.w, V[7], val);
        float ri = srw[r], cli = scl[r];
        float4 d;
        if (!leftblk) {
            float pen = ri * 10000.f + gm;
            d = make_float4(val.x - pen, val.y - pen, val.z - pen, val.w - pen);
        } else {
            float base = ri + cli;
            float px = ((c0 + 0) > i && base + rowc.x + colc.x == 0.f) ? 0.f : 10000.f;
            float py = ((c0 + 1) > i && base + rowc.y + colc.y == 0.f) ? 0.f : 10000.f;
            float pz = ((c0 + 2) > i && base + rowc.z + colc.z == 0.f) ? 0.f : 10000.f;
            float pw = ((c0 + 3) > i && base + rowc.w + colc.w == 0.f) ? 0.f : 10000.f;
            d = make_float4(val.x - px - gm, val.y - py - gm,
                            val.z - pz - gm, val.w - pw - gm);
        }
        float4 p;
        p.x = (d.x > -100.f) ? __expf(d.x) * rgs : 0.f;
        p.y = (d.y > -100.f) ? __expf(d.y) * rgs : 0.f;
        p.z = (d.z > -100.f) ? __expf(d.z) * rgs : 0.f;
        p.w = (d.w > -100.f) ? __expf(d.w) * rgs : 0.f;
        *(float4*)&Poss[(size_t)i * CN + c0] = p;
    }
}

// ---------------- launch ----------------
extern "C" void kernel_launch(void* const* d_in, const int* in_sizes, int n_in,
                              void* d_out, int out_size) {
    const float* h     = (const float*)d_in[0];
    const float* L     = (const float*)d_in[1];
    const float* Wp    = (const float*)d_in[2];
    const float* Pp    = (const float*)d_in[3];
    const float* Np    = (const float*)d_in[4];
    const float* G     = (const float*)d_in[5];
    const float* tag_w = (const float*)d_in[6];
    const float* tag_b = (const float*)d_in[7];
    const float* lin_w = (const float*)d_in[8];
    const float* lin_b = (const float*)d_in[9];
    float* Value = (float*)d_out;
    float* Poss  = Value + JC;

    k_init<<<16, 256>>>();
    k_rank<<<dim3(16, 16), 256>>>(h);
    k_scatter<<<16, 256>>>(h, L);
    k_sums<<<dim3(32, 32), 256>>>(G);
    k_fin1<<<16, 256>>>();
    k_prop<0><<<dim3(4, 32), 256>>>();
    k_fin2<<<16, 256>>>();
    k_prop<1><<<dim3(4, 32), 256>>>();
    k_fin3<<<16, 256>>>();
    k_vmat<<<32, 256>>>(tag_w, tag_b, lin_w, lin_b, Wp, Pp, Np);
    k_value<<<dim3(8, 64), 256>>>(Value);
    k_gred<<<1, 256>>>();
    k_poss<<<dim3(8, 64), 256>>>(Poss);
}

// round 4
// speedup vs baseline: 1.2590x; 1.1912x over previous
#include <cuda_runtime.h>
#include <math.h>

#define JN 4096
#define CN 8192
#define JC ((size_t)JN * (size_t)CN)
#define JW (JN / 32)          // 128 words per row of packed left-graph

// ---------------- device scratch (no allocations allowed) ----------------
__device__ int      g_rank[JN];
__device__ float    g_hs[JN], g_Ls[JN];
__device__ float    g_row[JN], g_colJ[JN], g_norm[JN];
// packed left JxJ graph: word (gg*4+k), bit lane  <->  column gg*128 + lane*4 + k
__device__ unsigned g_bits[JN][JW];
__device__ float    g_w1[3][JN];
__device__ float    g_w2[3][JN];
__device__ float    g_pp[32][3][JN];  // deterministic prop partials
__device__ float    g_U[JN][8];
__device__ float    g_V[8][CN];
__device__ float    g_bias[CN];
#define NPART 512
__device__ float g_pm[NPART], g_ps[NPART];
__device__ float g_gm, g_gs;

__device__ __forceinline__ float neg_inf() { return __int_as_float(0xff800000); }

__device__ __forceinline__ float4 f4fma(float a, float4 b, float4 c) {
    c.x = fmaf(a, b.x, c.x); c.y = fmaf(a, b.y, c.y);
    c.z = fmaf(a, b.z, c.z); c.w = fmaf(a, b.w, c.w);
    return c;
}

__device__ __forceinline__ void smupd(float& m, float& s, float t) {
    if (t > m) { s = s * __expf(m - t) + 1.f; m = t; }
    else { float d = t - m; if (d > -100.f) s += __expf(d); }
}

__device__ __forceinline__ void smcomb(float& m, float& s, float om, float os) {
    float nm = fmaxf(m, om);
    s = s * __expf(m - nm) + os * __expf(om - nm);
    m = nm;
}

// ---------------- kernels ----------------

__global__ void k_init() {
    int i = blockIdx.x * blockDim.x + threadIdx.x;
    if (i < JN) {
        g_rank[i] = 0;
        g_row[i] = 0.f; g_colJ[i] = 0.f;
    }
}

// rank[i] = #{j : h[j] > h[i]} + #{j : h[j]==h[i] && j<i}
__global__ void k_rank(const float* __restrict__ h) {
    __shared__ float sh[256];
    int t = threadIdx.x;
    int i = blockIdx.x * 256 + t;
    float hi = h[i];
    int jbase = blockIdx.y * 256;
    sh[t] = h[jbase + t];
    __syncthreads();
    int cnt = 0;
    #pragma unroll 8
    for (int k = 0; k < 256; k++) {
        float hj = sh[k];
        int j = jbase + k;
        cnt += (hj > hi) || (hj == hi && j < i);
    }
    atomicAdd(&g_rank[i], cnt);
}

__global__ void k_scatter(const float* __restrict__ h, const float* __restrict__ L) {
    int i = blockIdx.x * 256 + threadIdx.x;
    int r = g_rank[i];
    g_hs[r] = h[i];
    g_Ls[r] = L[i];
}

// Full-Graph pass, float4 loads, batched for MLP.
// Right half: REDUX row sums. Left half: 4 ballots -> bits + popc row sums + col sums.
// All accumulated values are exact small integers -> float atomics order-invariant.
__global__ void k_sums(const float* __restrict__ G) {
    int t = threadIdx.x;
    int lane = t & 31;
    int wi = t >> 5;
    int c0 = blockIdx.x * 1024;           // 1024 cols per block
    int j0 = blockIdx.y * 64;             // 64-row chunk
    bool left = (c0 < JN);
    const float4* gp = (const float4*)(G + (size_t)j0 * CN + c0) + t;

    float4 colacc = make_float4(0.f, 0.f, 0.f, 0.f);
    int rowacc0 = 0, rowacc1 = 0;
    int wbase = (c0 >> 5) + wi * 4;

    for (int r0 = 0; r0 < 64; r0 += 4) {
        float4 v[4];
        #pragma unroll
        for (int q = 0; q < 4; q++)
            v[q] = __ldcs(&gp[(size_t)(r0 + q) * (CN / 4)]);
        #pragma unroll
        for (int q = 0; q < 4; q++) {
            int r = r0 + q;
            int rs;
            if (left) {
                unsigned b0 = __ballot_sync(0xffffffffu, v[q].x != 0.f);
                unsigned b1 = __ballot_sync(0xffffffffu, v[q].y != 0.f);
                unsigned b2 = __ballot_sync(0xffffffffu, v[q].z != 0.f);
                unsigned b3 = __ballot_sync(0xffffffffu, v[q].w != 0.f);
                rs = __popc(b0) + __popc(b1) + __popc(b2) + __popc(b3);
                colacc.x += v[q].x; colacc.y += v[q].y;
                colacc.z += v[q].z; colacc.w += v[q].w;
                if (lane < 4) {
                    unsigned bb = lane == 0 ? b0 : lane == 1 ? b1 : lane == 2 ? b2 : b3;
                    g_bits[j0 + r][wbase + lane] = bb;
                }
            } else {
                int cnt = (v[q].x != 0.f) + (v[q].y != 0.f) +
                          (v[q].z != 0.f) + (v[q].w != 0.f);
                rs = __reduce_add_sync(0xffffffffu, (unsigned)cnt);
            }
            if (lane == (r & 31)) { if (r & 32) rowacc1 += rs; else rowacc0 += rs; }
        }
    }
    atomicAdd(&g_row[j0 + lane], (float)rowacc0);
    atomicAdd(&g_row[j0 + 32 + lane], (float)rowacc1);
    if (left) {
        int c = c0 + t * 4;
        atomicAdd(&g_colJ[c + 0], colacc.x);
        atomicAdd(&g_colJ[c + 1], colacc.y);
        atomicAdd(&g_colJ[c + 2], colacc.z);
        atomicAdd(&g_colJ[c + 3], colacc.w);
    }
}

__global__ void k_fin1() {
    int i = blockIdx.x * 256 + threadIdx.x;
    float n = rsqrtf(fmaxf(g_colJ[i], 1.f));
    g_norm[i] = n;
    g_w1[0][i] = n * g_hs[i];
    g_w1[1][i] = n * g_Ls[i];
    g_w1[2][i] = n;
}

// Bit-graph prop: partial[by][q][c] = sum_{j in chunk} bit(j,c) * w[q][j]
// Block: 1024 columns, 128-row chunk. 256 threads, 4 cols each.
template <int PASS>
__global__ void k_prop() {
    const float* w0 = PASS ? g_w2[0] : g_w1[0];
    const float* w1 = PASS ? g_w2[1] : g_w1[1];
    const float* w2 = PASS ? g_w2[2] : g_w1[2];
    __shared__ uint4 sw[128][8];       // 128 rows x 8 uint4 (32 words = 1024 cols)
    __shared__ float s0[128], s1[128], s2[128];
    int t = threadIdx.x;
    int c0 = blockIdx.x * 1024;
    int j0 = blockIdx.y * 128;

    for (int idx = t; idx < 128 * 8; idx += 256) {
        int row = idx >> 3, w = idx & 7;
        sw[row][w] = *(const uint4*)&g_bits[j0 + row][(c0 >> 5) + w * 4];
    }
    if (t < 128) {
        s0[t] = w0[j0 + t]; s1[t] = w1[j0 + t]; s2[t] = w2[j0 + t];
    }
    __syncthreads();

    int grp = t >> 5;              // uint4 slot (uniform per warp -> broadcast)
    int sh = t & 31;               // bit position for this thread
    float a0x=0,a0y=0,a0z=0,a0w=0;
    float a1x=0,a1y=0,a1z=0,a1w=0;
    float a2x=0,a2y=0,a2z=0,a2w=0;
    #pragma unroll 4
    for (int r = 0; r < 128; r++) {
        uint4 w4 = sw[r][grp];
        float u0 = s0[r], u1 = s1[r], u2 = s2[r];
        if ((w4.x >> sh) & 1u) { a0x += u0; a1x += u1; a2x += u2; }
        if ((w4.y >> sh) & 1u) { a0y += u0; a1y += u1; a2y += u2; }
        if ((w4.z >> sh) & 1u) { a0z += u0; a1z += u1; a2z += u2; }
        if ((w4.w >> sh) & 1u) { a0w += u0; a1w += u1; a2w += u2; }
    }
    int c = c0 + t * 4;
    *(float4*)&g_pp[blockIdx.y][0][c] = make_float4(a0x, a0y, a0z, a0w);
    *(float4*)&g_pp[blockIdx.y][1][c] = make_float4(a1x, a1y, a1z, a1w);
    *(float4*)&g_pp[blockIdx.y][2][c] = make_float4(a2x, a2y, a2z, a2w);
}

__global__ void k_fin2() {
    int i = blockIdx.x * 256 + threadIdx.x;
    float n = g_norm[i];
    float a = 0.f, b = 0.f, s = 0.f;
    #pragma unroll
    for (int p = 0; p < 32; p++) {
        a += g_pp[p][0][i];
        b += g_pp[p][1][i];
        s += g_pp[p][2][i];
    }
    float a1 = n * a, b1 = n * b, s1 = n * s;
    g_U[i][0] = g_hs[i];
    g_U[i][1] = g_Ls[i];
    g_U[i][2] = a1;
    g_U[i][3] = b1;
    g_U[i][4] = s1;
    g_w2[0][i] = n * a1;
    g_w2[1][i] = n * b1;
    g_w2[2][i] = n * s1;
}

__global__ void k_fin3() {
    int i = blockIdx.x * 256 + threadIdx.x;
    float n = g_norm[i];
    float a = 0.f, b = 0.f, s = 0.f;
    #pragma unroll
    for (int p = 0; p < 32; p++) {
        a += g_pp[p][0][i];
        b += g_pp[p][1][i];
        s += g_pp[p][2][i];
    }
    g_U[i][5] = n * a;
    g_U[i][6] = n * b;
    g_U[i][7] = n * s;
}

// V[8][CN], bias[CN] from tag_w(18x64)@lin_w(64xCN), tag_b, lin_b, scalars W,P,N
__global__ void k_vmat(const float* __restrict__ tag_w, const float* __restrict__ tag_b,
                       const float* __restrict__ lin_w, const float* __restrict__ lin_b,
                       const float* __restrict__ Wp, const float* __restrict__ Pp,
                       const float* __restrict__ Np) {
    __shared__ float stw[18 * 64];
    __shared__ float stb[64];
    int t = threadIdx.x;
    for (int k = t; k < 18 * 64; k += 256) stw[k] = tag_w[k];
    if (t < 64) stb[t] = tag_b[t];
    __syncthreads();
    int c = blockIdx.x * 256 + t;
    float m[18];
    #pragma unroll
    for (int q = 0; q < 18; q++) m[q] = 0.f;
    float tb = 0.f;
    for (int k = 0; k < 64; k++) {
        float lw = lin_w[(size_t)k * CN + c];
        #pragma unroll
        for (int q = 0; q < 18; q++) m[q] = fmaf(stw[q * 64 + k], lw, m[q]);
        tb = fmaf(stb[k], lw, tb);
    }
    float Wv = *Wp, Pv = *Pp, Nv = *Np;
    g_V[0][c] = m[0];
    g_V[1][c] = m[1];
    g_V[2][c] = m[6];
    g_V[3][c] = m[7];
    g_V[4][c] = Wv * m[8] + Pv * m[9] + Nv * m[10] + m[11];
    g_V[5][c] = m[12];
    g_V[6][c] = m[13];
    g_V[7][c] = Wv * m[14] + Pv * m[15] + Nv * m[16] + m[17];
    g_bias[c] = lin_b[c] + tb + Wv * m[2] + Pv * m[3] + Nv * m[4] + m[5];
}

#define VROWS 64
// Value = U @ V + bias; write Value; fused online-softmax stats on tmp = Value - pen
__global__ void k_value(float* __restrict__ Value) {
    __shared__ float4 sU2[VROWS][2];
    __shared__ float srw[VROWS], scl[VROWS];
    __shared__ float red_m[8], red_s[8];
    int t = threadIdx.x;
    int c0 = blockIdx.x * 1024 + t * 4;
    int i0 = blockIdx.y * VROWS;
    for (int k = t; k < VROWS * 2; k += 256)
        sU2[k >> 1][k & 1] = ((const float4*)g_U)[i0 * 2 + k];
    if (t < VROWS) { srw[t] = g_row[i0 + t]; scl[t] = g_colJ[i0 + t]; }
    __syncthreads();
    float4 V[8];
    #pragma unroll
    for (int q = 0; q < 8; q++) V[q] = *(const float4*)&g_V[q][c0];
    float4 bs = *(const float4*)&g_bias[c0];
    bool leftblk = (c0 < JN);
    float4 rowc = make_float4(0, 0, 0, 0), colc = make_float4(0, 0, 0, 0);
    if (leftblk) { rowc = *(const float4*)&g_row[c0]; colc = *(const float4*)&g_colJ[c0]; }
    float m = neg_inf(), s = 0.f;
    for (int r = 0; r < VROWS; r++) {
        int i = i0 + r;
        float4 u0 = sU2[r][0], u1 = sU2[r][1];
        float4 val = bs;
        val = f4fma(u0.x, V[0], val);
        val = f4fma(u0.y, V[1], val);
        val = f4fma(u0.z, V[2], val);
        val = f4fma(u0.w, V[3], val);
        val = f4fma(u1.x, V[4], val);
        val = f4fma(u1.y, V[5], val);
        val = f4fma(u1.z, V[6], val);
        val = f4fma(u1.w, V[7], val);
        __stcs((float4*)&Value[(size_t)i * CN + c0], val);
        float ri = srw[r], cli = scl[r];
        if (!leftblk) {
            float pen = ri * 10000.f;
            smupd(m, s, val.x - pen);
            smupd(m, s, val.y - pen);
            smupd(m, s, val.z - pen);
            smupd(m, s, val.w - pen);
        } else {
            float base = ri + cli;
            float px = ((c0 + 0) > i && base + rowc.x + colc.x == 0.f) ? 0.f : 10000.f;
            float py = ((c0 + 1) > i && base + rowc.y + colc.y == 0.f) ? 0.f : 10000.f;
            float pz = ((c0 + 2) > i && base + rowc.z + colc.z == 0.f) ? 0.f : 10000.f;
            float pw = ((c0 + 3) > i && base + rowc.w + colc.w == 0.f) ? 0.f : 10000.f;
            smupd(m, s, val.x - px);
            smupd(m, s, val.y - py);
            smupd(m, s, val.z - pz);
            smupd(m, s, val.w - pw);
        }
    }
    #pragma unroll
    for (int off = 16; off; off >>= 1) {
        float om = __shfl_xor_sync(0xffffffffu, m, off);
        float os = __shfl_xor_sync(0xffffffffu, s, off);
        smcomb(m, s, om, os);
    }
    if ((t & 31) == 0) { red_m[t >> 5] = m; red_s[t >> 5] = s; }
    __syncthreads();
    if (t == 0) {
        float M = red_m[0], S = red_s[0];
        for (int k = 1; k < 8; k++) smcomb(M, S, red_m[k], red_s[k]);
        int pid = blockIdx.y * gridDim.x + blockIdx.x;
        g_pm[pid] = M; g_ps[pid] = S;
    }
}

__global__ void k_gred() {
    __shared__ float rm[256], rs[256];
    int t = threadIdx.x;
    float m = neg_inf(), s = 0.f;
    for (int k = t; k < NPART; k += 256) smcomb(m, s, g_pm[k], g_ps[k]);
    rm[t] = m; rs[t] = s;
    __syncthreads();
    for (int w = 128; w; w >>= 1) {
        if (t < w) {
            float om = rm[t + w], os = rs[t + w];
            float mm = rm[t], ss = rs[t];
            smcomb(mm, ss, om, os);
            rm[t] = mm; rs[t] = ss;
        }
        __syncthreads();
    }
    if (t == 0) { g_gm = rm[0]; g_gs = rs[0]; }
}

// recompute Value (rank-8, cheaper than re-reading 128MB), write Poss
__global__ void k_poss(float* __restrict__ Poss) {
    __shared__ float4 sU2[VROWS][2];
    __shared__ float srw[VROWS], scl[VROWS];
    int t = threadIdx.x;
    int c0 = blockIdx.x * 1024 + t * 4;
    int i0 = blockIdx.y * VROWS;
    for (int k = t; k < VROWS * 2; k += 256)
        sU2[k >> 1][k & 1] = ((const float4*)g_U)[i0 * 2 + k];
    if (t < VROWS) { srw[t] = g_row[i0 + t]; scl[t] = g_colJ[i0 + t]; }
    __syncthreads();
    float4 V[8];
    #pragma unroll
    for (int q = 0; q < 8; q++) V[q] = *(const float4*)&g_V[q][c0];
    float4 bs = *(const float4*)&g_bias[c0];
    bool leftblk = (c0 < JN);
    float4 rowc = make_float4(0, 0, 0, 0), colc = make_float4(0, 0, 0, 0);
    if (leftblk) { rowc = *(const float4*)&g_row[c0]; colc = *(const float4*)&g_colJ[c0]; }
    float gm = g_gm;
    float rgs = 1.f / g_gs;
    for (int r = 0; r < VROWS; r++) {
        int i = i0 + r;
        float4 u0 = sU2[r][0], u1 = sU2[r][1];
        float4 val = bs;
        val = f4fma(u0.x, V[0], val);
        val = f4fma(u0.y, V[1], val);
        val = f4fma(u0.z, V[2], val);
        val = f4fma(u0.w, V[3], val);
        val = f4fma(u1.x, V[4], val);
        val = f4fma(u1.y, V[5], val);
        val = f4fma(u1.z, V[6], val);
        val = f4fma(u1.w, V[7], val);
        float ri = srw[r], cli = scl[r];
        float4 d;
        if (!leftblk) {
            float pen = ri * 10000.f + gm;
            d = make_float4(val.x - pen, val.y - pen, val.z - pen, val.w - pen);
        } else {
            float base = ri + cli;
            float px = ((c0 + 0) > i && base + rowc.x + colc.x == 0.f) ? 0.f : 10000.f;
            float py = ((c0 + 1) > i && base + rowc.y + colc.y == 0.f) ? 0.f : 10000.f;
            float pz = ((c0 + 2) > i && base + rowc.z + colc.z == 0.f) ? 0.f : 10000.f;
            float pw = ((c0 + 3) > i && base + rowc.w + colc.w == 0.f) ? 0.f : 10000.f;
            d = make_float4(val.x - px - gm, val.y - py - gm,
                            val.z - pz - gm, val.w - pw - gm);
        }
        float4 p;
        p.x = (d.x > -100.f) ? __expf(d.x) * rgs : 0.f;
        p.y = (d.y > -100.f) ? __expf(d.y) * rgs : 0.f;
        p.z = (d.z > -100.f) ? __expf(d.z) * rgs : 0.f;
        p.w = (d.w > -100.f) ? __expf(d.w) * rgs : 0.f;
        __stcs((float4*)&Poss[(size_t)i * CN + c0], p);
    }
}

// ---------------- launch ----------------
extern "C" void kernel_launch(void* const* d_in, const int* in_sizes, int n_in,
                              void* d_out, int out_size) {
    const float* h     = (const float*)d_in[0];
    const float* L     = (const float*)d_in[1];
    const float* Wp    = (const float*)d_in[2];
    const float* Pp    = (const float*)d_in[3];
    const float* Np    = (const float*)d_in[4];
    const float* G     = (const float*)d_in[5];
    const float* tag_w = (const float*)d_in[6];
    const float* tag_b = (const float*)d_in[7];
    const float* lin_w = (const float*)d_in[8];
    const float* lin_b = (const float*)d_in[9];
    float* Value = (float*)d_out;
    float* Poss  = Value + JC;

    k_init<<<16, 256>>>();
    k_rank<<<dim3(16, 16), 256>>>(h);
    k_scatter<<<16, 256>>>(h, L);
    k_sums<<<dim3(8, 64), 256>>>(G);
    k_fin1<<<16, 256>>>();
    k_prop<0><<<dim3(4, 32), 256>>>();
    k_fin2<<<16, 256>>>();
    k_prop<1><<<dim3(4, 32), 256>>>();
    k_fin3<<<16, 256>>>();
    k_vmat<<<32, 256>>>(tag_w, tag_b, lin_w, lin_b, Wp, Pp, Np);
    k_value<<<dim3(8, 64), 256>>>(Value);
    k_gred<<<1, 256>>>();
    k_poss<<<dim3(8, 64), 256>>>(Poss);
}

// round 5
// speedup vs baseline: 1.3492x; 1.0717x over previous
#include <cuda_runtime.h>
#include <math.h>

#define JN 4096
#define CN 8192
#define JC ((size_t)JN * (size_t)CN)
#define JW (JN / 32)          // 128 words per row of packed left-graph

// ---------------- device scratch (no allocations allowed) ----------------
__device__ int      g_rank[JN];
__device__ float    g_hs[JN], g_Ls[JN];
__device__ float    g_row[JN], g_colJ[JN], g_norm[JN];
// packed left JxJ graph: word (gg*4+k), bit lane  <->  column gg*128 + lane*4 + k
__device__ unsigned g_bits[JN][JW];
__device__ float    g_w1[3][JN];
__device__ float    g_w2[3][JN];
__device__ float    g_pp[32][3][JN];  // deterministic prop partials
__device__ float    g_U[JN][8];
__device__ float    g_V[8][CN];
__device__ float    g_bias[CN];
#define NPART 1024
__device__ float g_pm[NPART], g_ps[NPART];
__device__ float g_gm, g_gs;

__device__ __forceinline__ float neg_inf() { return __int_as_float(0xff800000); }

__device__ __forceinline__ float4 f4fma(float a, float4 b, float4 c) {
    c.x = fmaf(a, b.x, c.x); c.y = fmaf(a, b.y, c.y);
    c.z = fmaf(a, b.z, c.z); c.w = fmaf(a, b.w, c.w);
    return c;
}

__device__ __forceinline__ void smupd(float& m, float& s, float t) {
    if (t > m) { s = s * __expf(m - t) + 1.f; m = t; }
    else { float d = t - m; if (d > -100.f) s += __expf(d); }
}

__device__ __forceinline__ void smcomb(float& m, float& s, float om, float os) {
    float nm = fmaxf(m, om);
    s = s * __expf(m - nm) + os * __expf(om - nm);
    m = nm;
}

// ---------------- kernels ----------------

__global__ void k_init() {
    int i = blockIdx.x * blockDim.x + threadIdx.x;
    if (i < JN) {
        g_rank[i] = 0;
        g_row[i] = 0.f; g_colJ[i] = 0.f;
    }
}

// rank[i] = #{j : h[j] > h[i]} + #{j : h[j]==h[i] && j<i}
__global__ void k_rank(const float* __restrict__ h) {
    __shared__ float sh[256];
    int t = threadIdx.x;
    int i = blockIdx.x * 256 + t;
    float hi = h[i];
    int jbase = blockIdx.y * 256;
    sh[t] = h[jbase + t];
    __syncthreads();
    int cnt = 0;
    #pragma unroll 8
    for (int k = 0; k < 256; k++) {
        float hj = sh[k];
        int j = jbase + k;
        cnt += (hj > hi) || (hj == hi && j < i);
    }
    atomicAdd(&g_rank[i], cnt);
}

__global__ void k_scatter(const float* __restrict__ h, const float* __restrict__ L) {
    int i = blockIdx.x * 256 + threadIdx.x;
    int r = g_rank[i];
    g_hs[r] = h[i];
    g_Ls[r] = L[i];
}

// Full-Graph pass, float4 loads, 8-deep batches for MLP, 32-row chunks for occupancy.
// Right half: REDUX row sums. Left half: 4 ballots -> bits + popc row sums + col sums.
// All accumulated values are exact small integers -> float atomics order-invariant.
__global__ void k_sums(const float* __restrict__ G) {
    int t = threadIdx.x;
    int lane = t & 31;
    int wi = t >> 5;
    int c0 = blockIdx.x * 1024;           // 1024 cols per block
    int j0 = blockIdx.y * 32;             // 32-row chunk
    bool left = (c0 < JN);
    const float4* gp = (const float4*)(G + (size_t)j0 * CN + c0) + t;

    float4 colacc = make_float4(0.f, 0.f, 0.f, 0.f);
    int rowacc = 0;
    int wbase = (c0 >> 5) + wi * 4;

    #pragma unroll
    for (int r0 = 0; r0 < 32; r0 += 8) {
        float4 v[8];
        #pragma unroll
        for (int q = 0; q < 8; q++)
            v[q] = __ldcs(&gp[(size_t)(r0 + q) * (CN / 4)]);
        #pragma unroll
        for (int q = 0; q < 8; q++) {
            int r = r0 + q;
            int rs;
            if (left) {
                unsigned b0 = __ballot_sync(0xffffffffu, v[q].x != 0.f);
                unsigned b1 = __ballot_sync(0xffffffffu, v[q].y != 0.f);
                unsigned b2 = __ballot_sync(0xffffffffu, v[q].z != 0.f);
                unsigned b3 = __ballot_sync(0xffffffffu, v[q].w != 0.f);
                rs = __popc(b0) + __popc(b1) + __popc(b2) + __popc(b3);
                colacc.x += v[q].x; colacc.y += v[q].y;
                colacc.z += v[q].z; colacc.w += v[q].w;
                if (lane < 4) {
                    unsigned bb = lane == 0 ? b0 : lane == 1 ? b1 : lane == 2 ? b2 : b3;
                    g_bits[j0 + r][wbase + lane] = bb;
                }
            } else {
                int cnt = (v[q].x != 0.f) + (v[q].y != 0.f) +
                          (v[q].z != 0.f) + (v[q].w != 0.f);
                rs = __reduce_add_sync(0xffffffffu, (unsigned)cnt);
            }
            if (lane == r) rowacc += rs;
        }
    }
    atomicAdd(&g_row[j0 + lane], (float)rowacc);
    if (left) {
        int c = c0 + t * 4;
        atomicAdd(&g_colJ[c + 0], colacc.x);
        atomicAdd(&g_colJ[c + 1], colacc.y);
        atomicAdd(&g_colJ[c + 2], colacc.z);
        atomicAdd(&g_colJ[c + 3], colacc.w);
    }
}

__global__ void k_fin1() {
    int i = blockIdx.x * 256 + threadIdx.x;
    float n = rsqrtf(fmaxf(g_colJ[i], 1.f));
    g_norm[i] = n;
    g_w1[0][i] = n * g_hs[i];
    g_w1[1][i] = n * g_Ls[i];
    g_w1[2][i] = n;
}

// Bit-graph prop: partial[by][q][c] = sum_{j in chunk} bit(j,c) * w[q][j]
// Block: 1024 columns, 128-row chunk. 256 threads, 4 cols each.
template <int PASS>
__global__ void k_prop() {
    const float* w0 = PASS ? g_w2[0] : g_w1[0];
    const float* w1 = PASS ? g_w2[1] : g_w1[1];
    const float* w2 = PASS ? g_w2[2] : g_w1[2];
    __shared__ uint4 sw[128][8];       // 128 rows x 8 uint4 (32 words = 1024 cols)
    __shared__ float s0[128], s1[128], s2[128];
    int t = threadIdx.x;
    int c0 = blockIdx.x * 1024;
    int j0 = blockIdx.y * 128;

    for (int idx = t; idx < 128 * 8; idx += 256) {
        int row = idx >> 3, w = idx & 7;
        sw[row][w] = *(const uint4*)&g_bits[j0 + row][(c0 >> 5) + w * 4];
    }
    if (t < 128) {
        s0[t] = w0[j0 + t]; s1[t] = w1[j0 + t]; s2[t] = w2[j0 + t];
    }
    __syncthreads();

    int grp = t >> 5;              // uint4 slot (uniform per warp -> broadcast)
    int sh = t & 31;               // bit position for this thread
    float a0x=0,a0y=0,a0z=0,a0w=0;
    float a1x=0,a1y=0,a1z=0,a1w=0;
    float a2x=0,a2y=0,a2z=0,a2w=0;
    #pragma unroll 4
    for (int r = 0; r < 128; r++) {
        uint4 w4 = sw[r][grp];
        float u0 = s0[r], u1 = s1[r], u2 = s2[r];
        if ((w4.x >> sh) & 1u) { a0x += u0; a1x += u1; a2x += u2; }
        if ((w4.y >> sh) & 1u) { a0y += u0; a1y += u1; a2y += u2; }
        if ((w4.z >> sh) & 1u) { a0z += u0; a1z += u1; a2z += u2; }
        if ((w4.w >> sh) & 1u) { a0w += u0; a1w += u1; a2w += u2; }
    }
    int c = c0 + t * 4;
    *(float4*)&g_pp[blockIdx.y][0][c] = make_float4(a0x, a0y, a0z, a0w);
    *(float4*)&g_pp[blockIdx.y][1][c] = make_float4(a1x, a1y, a1z, a1w);
    *(float4*)&g_pp[blockIdx.y][2][c] = make_float4(a2x, a2y, a2z, a2w);
}

__global__ void k_fin2() {
    int i = blockIdx.x * 256 + threadIdx.x;
    float n = g_norm[i];
    float a = 0.f, b = 0.f, s = 0.f;
    #pragma unroll
    for (int p = 0; p < 32; p++) {
        a += g_pp[p][0][i];
        b += g_pp[p][1][i];
        s += g_pp[p][2][i];
    }
    float a1 = n * a, b1 = n * b, s1 = n * s;
    g_U[i][0] = g_hs[i];
    g_U[i][1] = g_Ls[i];
    g_U[i][2] = a1;
    g_U[i][3] = b1;
    g_U[i][4] = s1;
    g_w2[0][i] = n * a1;
    g_w2[1][i] = n * b1;
    g_w2[2][i] = n * s1;
}

__global__ void k_fin3() {
    int i = blockIdx.x * 256 + threadIdx.x;
    float n = g_norm[i];
    float a = 0.f, b = 0.f, s = 0.f;
    #pragma unroll
    for (int p = 0; p < 32; p++) {
        a += g_pp[p][0][i];
        b += g_pp[p][1][i];
        s += g_pp[p][2][i];
    }
    g_U[i][5] = n * a;
    g_U[i][6] = n * b;
    g_U[i][7] = n * s;
}

// V[8][CN], bias[CN] from tag_w(18x64)@lin_w(64xCN), tag_b, lin_b, scalars W,P,N
__global__ void k_vmat(const float* __restrict__ tag_w, const float* __restrict__ tag_b,
                       const float* __restrict__ lin_w, const float* __restrict__ lin_b,
                       const float* __restrict__ Wp, const float* __restrict__ Pp,
                       const float* __restrict__ Np) {
    __shared__ float stw[18 * 64];
    __shared__ float stb[64];
    int t = threadIdx.x;
    for (int k = t; k < 18 * 64; k += 256) stw[k] = tag_w[k];
    if (t < 64) stb[t] = tag_b[t];
    __syncthreads();
    int c = blockIdx.x * 256 + t;
    float m[18];
    #pragma unroll
    for (int q = 0; q < 18; q++) m[q] = 0.f;
    float tb = 0.f;
    for (int k = 0; k < 64; k++) {
        float lw = lin_w[(size_t)k * CN + c];
        #pragma unroll
        for (int q = 0; q < 18; q++) m[q] = fmaf(stw[q * 64 + k], lw, m[q]);
        tb = fmaf(stb[k], lw, tb);
    }
    float Wv = *Wp, Pv = *Pp, Nv = *Np;
    g_V[0][c] = m[0];
    g_V[1][c] = m[1];
    g_V[2][c] = m[6];
    g_V[3][c] = m[7];
    g_V[4][c] = Wv * m[8] + Pv * m[9] + Nv * m[10] + m[11];
    g_V[5][c] = m[12];
    g_V[6][c] = m[13];
    g_V[7][c] = Wv * m[14] + Pv * m[15] + Nv * m[16] + m[17];
    g_bias[c] = lin_b[c] + tb + Wv * m[2] + Pv * m[3] + Nv * m[4] + m[5];
}

#define VROWS 32
// Value = U @ V + bias; write Value; fused online-softmax stats on tmp = Value - pen
__global__ void k_value(float* __restrict__ Value) {
    __shared__ float4 sU2[VROWS][2];
    __shared__ float srw[VROWS], scl[VROWS];
    __shared__ float red_m[8], red_s[8];
    int t = threadIdx.x;
    int c0 = blockIdx.x * 1024 + t * 4;
    int i0 = blockIdx.y * VROWS;
    if (t < VROWS * 2)
        sU2[t >> 1][t & 1] = ((const float4*)g_U)[i0 * 2 + t];
    if (t < VROWS) { srw[t] = g_row[i0 + t]; scl[t] = g_colJ[i0 + t]; }
    __syncthreads();
    float4 V[8];
    #pragma unroll
    for (int q = 0; q < 8; q++) V[q] = *(const float4*)&g_V[q][c0];
    float4 bs = *(const float4*)&g_bias[c0];
    bool leftblk = (c0 < JN);
    float4 rowc = make_float4(0, 0, 0, 0), colc = make_float4(0, 0, 0, 0);
    if (leftblk) { rowc = *(const float4*)&g_row[c0]; colc = *(const float4*)&g_colJ[c0]; }
    float m = neg_inf(), s = 0.f;
    for (int r = 0; r < VROWS; r++) {
        int i = i0 + r;
        float4 u0 = sU2[r][0], u1 = sU2[r][1];
        float4 val = bs;
        val = f4fma(u0.x, V[0], val);
        val = f4fma(u0.y, V[1], val);
        val = f4fma(u0.z, V[2], val);
        val = f4fma(u0.w, V[3], val);
        val = f4fma(u1.x, V[4], val);
        val = f4fma(u1.y, V[5], val);
        val = f4fma(u1.z, V[6], val);
        val = f4fma(u1.w, V[7], val);
        __stcs((float4*)&Value[(size_t)i * CN + c0], val);
        float ri = srw[r], cli = scl[r];
        if (!leftblk) {
            float pen = ri * 10000.f;
            smupd(m, s, val.x - pen);
            smupd(m, s, val.y - pen);
            smupd(m, s, val.z - pen);
            smupd(m, s, val.w - pen);
        } else {
            float base = ri + cli;
            float px = ((c0 + 0) > i && base + rowc.x + colc.x == 0.f) ? 0.f : 10000.f;
            float py = ((c0 + 1) > i && base + rowc.y + colc.y == 0.f) ? 0.f : 10000.f;
            float pz = ((c0 + 2) > i && base + rowc.z + colc.z == 0.f) ? 0.f : 10000.f;
            float pw = ((c0 + 3) > i && base + rowc.w + colc.w == 0.f) ? 0.f : 10000.f;
            smupd(m, s, val.x - px);
            smupd(m, s, val.y - py);
            smupd(m, s, val.z - pz);
            smupd(m, s, val.w - pw);
        }
    }
    #pragma unroll
    for (int off = 16; off; off >>= 1) {
        float om = __shfl_xor_sync(0xffffffffu, m, off);
        float os = __shfl_xor_sync(0xffffffffu, s, off);
        smcomb(m, s, om, os);
    }
    if ((t & 31) == 0) { red_m[t >> 5] = m; red_s[t >> 5] = s; }
    __syncthreads();
    if (t == 0) {
        float M = red_m[0], S = red_s[0];
        for (int k = 1; k < 8; k++) smcomb(M, S, red_m[k], red_s[k]);
        int pid = blockIdx.y * gridDim.x + blockIdx.x;
        g_pm[pid] = M; g_ps[pid] = S;
    }
}

__global__ void k_gred() {
    __shared__ float rm[256], rs[256];
    int t = threadIdx.x;
    float m = neg_inf(), s = 0.f;
    for (int k = t; k < NPART; k += 256) smcomb(m, s, g_pm[k], g_ps[k]);
    rm[t] = m; rs[t] = s;
    __syncthreads();
    for (int w = 128; w; w >>= 1) {
        if (t < w) {
            float om = rm[t + w], os = rs[t + w];
            float mm = rm[t], ss = rs[t];
            smcomb(mm, ss, om, os);
            rm[t] = mm; rs[t] = ss;
        }
        __syncthreads();
    }
    if (t == 0) { g_gm = rm[0]; g_gs = rs[0]; }
}

// recompute Value (rank-8, cheaper than re-reading 128MB), write Poss
__global__ void k_poss(float* __restrict__ Poss) {
    __shared__ float4 sU2[VROWS][2];
    __shared__ float srw[VROWS], scl[VROWS];
    int t = threadIdx.x;
    int c0 = blockIdx.x * 1024 + t * 4;
    int i0 = blockIdx.y * VROWS;
    if (t < VROWS * 2)
        sU2[t >> 1][t & 1] = ((const float4*)g_U)[i0 * 2 + t];
    if (t < VROWS) { srw[t] = g_row[i0 + t]; scl[t] = g_colJ[i0 + t]; }
    __syncthreads();
    float4 V[8];
    #pragma unroll
    for (int q = 0; q < 8; q++) V[q] = *(const float4*)&g_V[q][c0];
    float4 bs = *(const float4*)&g_bias[c0];
    bool leftblk = (c0 < JN);
    float4 rowc = make_float4(0, 0, 0, 0), colc = make_float4(0, 0, 0, 0);
    if (leftblk) { rowc = *(const float4*)&g_row[c0]; colc = *(const float4*)&g_colJ[c0]; }
    float gm = g_gm;
    float rgs = 1.f / g_gs;
    for (int r = 0; r < VROWS; r++) {
        int i = i0 + r;
        float4 u0 = sU2[r][0], u1 = sU2[r][1];
        float4 val = bs;
        val = f4fma(u0.x, V[0], val);
        val = f4fma(u0.y, V[1], val);
        val = f4fma(u0.z, V[2], val);
        val = f4fma(u0.w, V[3], val);
        val = f4fma(u1.x, V[4], val);
        val = f4fma(u1.y, V[5], val);
        val = f4fma(u1.z, V[6], val);
        val = f4fma(u1.w, V[7], val);
        float ri = srw[r], cli = scl[r];
        float4 d;
        if (!leftblk) {
            float pen = ri * 10000.f + gm;
            d = make_float4(val.x - pen, val.y - pen, val.z - pen, val.w - pen);
        } else {
            float base = ri + cli;
            float px = ((c0 + 0) > i && base + rowc.x + colc.x == 0.f) ? 0.f : 10000.f;
            float py = ((c0 + 1) > i && base + rowc.y + colc.y == 0.f) ? 0.f : 10000.f;
            float pz = ((c0 + 2) > i && base + rowc.z + colc.z == 0.f) ? 0.f : 10000.f;
            float pw = ((c0 + 3) > i && base + rowc.w + colc.w == 0.f) ? 0.f : 10000.f;
            d = make_float4(val.x - px - gm, val.y - py - gm,
                            val.z - pz - gm, val.w - pw - gm);
        }
        float4 p;
        p.x = (d.x > -100.f) ? __expf(d.x) * rgs : 0.f;
        p.y = (d.y > -100.f) ? __expf(d.y) * rgs : 0.f;
        p.z = (d.z > -100.f) ? __expf(d.z) * rgs : 0.f;
        p.w = (d.w > -100.f) ? __expf(d.w) * rgs : 0.f;
        __stcs((float4*)&Poss[(size_t)i * CN + c0], p);
    }
}

// ---------------- launch ----------------
extern "C" void kernel_launch(void* const* d_in, const int* in_sizes, int n_in,
                              void* d_out, int out_size) {
    const float* h     = (const float*)d_in[0];
    const float* L     = (const float*)d_in[1];
    const float* Wp    = (const float*)d_in[2];
    const float* Pp    = (const float*)d_in[3];
    const float* Np    = (const float*)d_in[4];
    const float* G     = (const float*)d_in[5];
    const float* tag_w = (const float*)d_in[6];
    const float* tag_b = (const float*)d_in[7];
    const float* lin_w = (const float*)d_in[8];
    const float* lin_b = (const float*)d_in[9];
    float* Value = (float*)d_out;
    float* Poss  = Value + JC;

    k_init<<<16, 256>>>();
    k_rank<<<dim3(16, 16), 256>>>(h);
    k_scatter<<<16, 256>>>(h, L);
    k_sums<<<dim3(8, 128), 256>>>(G);
    k_fin1<<<16, 256>>>();
    k_prop<0><<<dim3(4, 32), 256>>>();
    k_fin2<<<16, 256>>>();
    k_prop<1><<<dim3(4, 32), 256>>>();
    k_fin3<<<16, 256>>>();
    k_vmat<<<32, 256>>>(tag_w, tag_b, lin_w, lin_b, Wp, Pp, Np);
    k_value<<<dim3(8, 128), 256>>>(Value);
    k_gred<<<1, 256>>>();
    k_poss<<<dim3(8, 128), 256>>>(Poss);
}

// round 6
// speedup vs baseline: 1.3500x; 1.0006x over previous
#include <cuda_runtime.h>
#include <math.h>

#define JN 4096
#define CN 8192
#define JC ((size_t)JN * (size_t)CN)
#define JW (JN / 32)          // 128 words per row of packed left-graph

// ---------------- device scratch (no allocations allowed) ----------------
__device__ int      g_rank[JN];
__device__ float    g_hs[JN], g_Ls[JN];
__device__ float    g_row[JN], g_colJ[JN], g_norm[JN];
// packed left JxJ graph: word (gg*4+k), bit lane  <->  column gg*128 + lane*4 + k
__device__ unsigned g_bits[JN][JW];
__device__ float    g_w1[3][JN];
__device__ float    g_w2[3][JN];
__device__ float    g_pp[32][3][JN];  // deterministic prop partials
__device__ float    g_U[JN][8];
__device__ float    g_V[8][CN];
__device__ float    g_bias[CN];
#define NPART 1024
__device__ float g_pm[NPART], g_ps[NPART];
__device__ float g_gm, g_gs;

__device__ __forceinline__ float neg_inf() { return __int_as_float(0xff800000); }

__device__ __forceinline__ float4 f4fma(float a, float4 b, float4 c) {
    c.x = fmaf(a, b.x, c.x); c.y = fmaf(a, b.y, c.y);
    c.z = fmaf(a, b.z, c.z); c.w = fmaf(a, b.w, c.w);
    return c;
}

__device__ __forceinline__ void smupd(float& m, float& s, float t) {
    if (t > m) { s = s * __expf(m - t) + 1.f; m = t; }
    else { float d = t - m; if (d > -100.f) s += __expf(d); }
}

__device__ __forceinline__ void smcomb(float& m, float& s, float om, float os) {
    float nm = fmaxf(m, om);
    s = s * __expf(m - nm) + os * __expf(om - nm);
    m = nm;
}

// ---------------- kernels ----------------

__global__ void k_init() {
    int i = blockIdx.x * blockDim.x + threadIdx.x;
    if (i < JN) {
        g_rank[i] = 0;
        g_row[i] = 0.f; g_colJ[i] = 0.f;
    }
}

// rank[i] = #{j : h[j] > h[i]} + #{j : h[j]==h[i] && j<i}
__global__ void k_rank(const float* __restrict__ h) {
    __shared__ float sh[256];
    int t = threadIdx.x;
    int i = blockIdx.x * 256 + t;
    float hi = h[i];
    int jbase = blockIdx.y * 256;
    sh[t] = h[jbase + t];
    __syncthreads();
    int cnt = 0;
    #pragma unroll 8
    for (int k = 0; k < 256; k++) {
        float hj = sh[k];
        int j = jbase + k;
        cnt += (hj > hi) || (hj == hi && j < i);
    }
    atomicAdd(&g_rank[i], cnt);
}

__global__ void k_scatter(const float* __restrict__ h, const float* __restrict__ L) {
    int i = blockIdx.x * 256 + threadIdx.x;
    int r = g_rank[i];
    g_hs[r] = h[i];
    g_Ls[r] = L[i];
}

// Full-Graph pass, float4 loads, 8-deep batches for MLP, 32-row chunks for occupancy.
// Right half: REDUX row sums. Left half: 4 ballots -> bits + popc row sums + col sums.
// All accumulated values are exact small integers -> float atomics order-invariant.
__global__ void k_sums(const float* __restrict__ G) {
    int t = threadIdx.x;
    int lane = t & 31;
    int wi = t >> 5;
    int c0 = blockIdx.x * 1024;           // 1024 cols per block
    int j0 = blockIdx.y * 32;             // 32-row chunk
    bool left = (c0 < JN);
    const float4* gp = (const float4*)(G + (size_t)j0 * CN + c0) + t;

    float4 colacc = make_float4(0.f, 0.f, 0.f, 0.f);
    int rowacc = 0;
    int wbase = (c0 >> 5) + wi * 4;

    #pragma unroll
    for (int r0 = 0; r0 < 32; r0 += 8) {
        float4 v[8];
        #pragma unroll
        for (int q = 0; q < 8; q++)
            v[q] = __ldcs(&gp[(size_t)(r0 + q) * (CN / 4)]);
        #pragma unroll
        for (int q = 0; q < 8; q++) {
            int r = r0 + q;
            int rs;
            if (left) {
                unsigned b0 = __ballot_sync(0xffffffffu, v[q].x != 0.f);
                unsigned b1 = __ballot_sync(0xffffffffu, v[q].y != 0.f);
                unsigned b2 = __ballot_sync(0xffffffffu, v[q].z != 0.f);
                unsigned b3 = __ballot_sync(0xffffffffu, v[q].w != 0.f);
                rs = __popc(b0) + __popc(b1) + __popc(b2) + __popc(b3);
                colacc.x += v[q].x; colacc.y += v[q].y;
                colacc.z += v[q].z; colacc.w += v[q].w;
                if (lane < 4) {
                    unsigned bb = lane == 0 ? b0 : lane == 1 ? b1 : lane == 2 ? b2 : b3;
                    g_bits[j0 + r][wbase + lane] = bb;
                }
            } else {
                int cnt = (v[q].x != 0.f) + (v[q].y != 0.f) +
                          (v[q].z != 0.f) + (v[q].w != 0.f);
                rs = __reduce_add_sync(0xffffffffu, (unsigned)cnt);
            }
            if (lane == r) rowacc += rs;
        }
    }
    atomicAdd(&g_row[j0 + lane], (float)rowacc);
    if (left) {
        int c = c0 + t * 4;
        atomicAdd(&g_colJ[c + 0], colacc.x);
        atomicAdd(&g_colJ[c + 1], colacc.y);
        atomicAdd(&g_colJ[c + 2], colacc.z);
        atomicAdd(&g_colJ[c + 3], colacc.w);
    }
}

__global__ void k_fin1() {
    int i = blockIdx.x * 256 + threadIdx.x;
    float n = rsqrtf(fmaxf(g_colJ[i], 1.f));
    g_norm[i] = n;
    g_w1[0][i] = n * g_hs[i];
    g_w1[1][i] = n * g_Ls[i];
    g_w1[2][i] = n;
}

// Bit-graph prop: partial[by][q][c] = sum_{j in chunk} bit(j,c) * w[q][j]
// Block: 1024 columns, 128-row chunk. 256 threads, 4 cols each.
template <int PASS>
__global__ void k_prop() {
    const float* w0 = PASS ? g_w2[0] : g_w1[0];
    const float* w1 = PASS ? g_w2[1] : g_w1[1];
    const float* w2 = PASS ? g_w2[2] : g_w1[2];
    __shared__ uint4 sw[128][8];       // 128 rows x 8 uint4 (32 words = 1024 cols)
    __shared__ float s0[128], s1[128], s2[128];
    int t = threadIdx.x;
    int c0 = blockIdx.x * 1024;
    int j0 = blockIdx.y * 128;

    for (int idx = t; idx < 128 * 8; idx += 256) {
        int row = idx >> 3, w = idx & 7;
        sw[row][w] = *(const uint4*)&g_bits[j0 + row][(c0 >> 5) + w * 4];
    }
    if (t < 128) {
        s0[t] = w0[j0 + t]; s1[t] = w1[j0 + t]; s2[t] = w2[j0 + t];
    }
    __syncthreads();

    int grp = t >> 5;              // uint4 slot (uniform per warp -> broadcast)
    int sh = t & 31;               // bit position for this thread
    float a0x=0,a0y=0,a0z=0,a0w=0;
    float a1x=0,a1y=0,a1z=0,a1w=0;
    float a2x=0,a2y=0,a2z=0,a2w=0;
    #pragma unroll 4
    for (int r = 0; r < 128; r++) {
        uint4 w4 = sw[r][grp];
        float u0 = s0[r], u1 = s1[r], u2 = s2[r];
        if ((w4.x >> sh) & 1u) { a0x += u0; a1x += u1; a2x += u2; }
        if ((w4.y >> sh) & 1u) { a0y += u0; a1y += u1; a2y += u2; }
        if ((w4.z >> sh) & 1u) { a0z += u0; a1z += u1; a2z += u2; }
        if ((w4.w >> sh) & 1u) { a0w += u0; a1w += u1; a2w += u2; }
    }
    int c = c0 + t * 4;
    *(float4*)&g_pp[blockIdx.y][0][c] = make_float4(a0x, a0y, a0z, a0w);
    *(float4*)&g_pp[blockIdx.y][1][c] = make_float4(a1x, a1y, a1z, a1w);
    *(float4*)&g_pp[blockIdx.y][2][c] = make_float4(a2x, a2y, a2z, a2w);
}

__global__ void k_fin2() {
    int i = blockIdx.x * 256 + threadIdx.x;
    float n = g_norm[i];
    float a = 0.f, b = 0.f, s = 0.f;
    #pragma unroll
    for (int p = 0; p < 32; p++) {
        a += g_pp[p][0][i];
        b += g_pp[p][1][i];
        s += g_pp[p][2][i];
    }
    float a1 = n * a, b1 = n * b, s1 = n * s;
    g_U[i][0] = g_hs[i];
    g_U[i][1] = g_Ls[i];
    g_U[i][2] = a1;
    g_U[i][3] = b1;
    g_U[i][4] = s1;
    g_w2[0][i] = n * a1;
    g_w2[1][i] = n * b1;
    g_w2[2][i] = n * s1;
}

__global__ void k_fin3() {
    int i = blockIdx.x * 256 + threadIdx.x;
    float n = g_norm[i];
    float a = 0.f, b = 0.f, s = 0.f;
    #pragma unroll
    for (int p = 0; p < 32; p++) {
        a += g_pp[p][0][i];
        b += g_pp[p][1][i];
        s += g_pp[p][2][i];
    }
    g_U[i][5] = n * a;
    g_U[i][6] = n * b;
    g_U[i][7] = n * s;
}

// V[8][CN], bias[CN] from tag_w(18x64)@lin_w(64xCN), tag_b, lin_b, scalars W,P,N
__global__ void k_vmat(const float* __restrict__ tag_w, const float* __restrict__ tag_b,
                       const float* __restrict__ lin_w, const float* __restrict__ lin_b,
                       const float* __restrict__ Wp, const float* __restrict__ Pp,
                       const float* __restrict__ Np) {
    __shared__ float stw[18 * 64];
    __shared__ float stb[64];
    int t = threadIdx.x;
    for (int k = t; k < 18 * 64; k += 256) stw[k] = tag_w[k];
    if (t < 64) stb[t] = tag_b[t];
    __syncthreads();
    int c = blockIdx.x * 256 + t;
    float m[18];
    #pragma unroll
    for (int q = 0; q < 18; q++) m[q] = 0.f;
    float tb = 0.f;
    for (int k = 0; k < 64; k++) {
        float lw = lin_w[(size_t)k * CN + c];
        #pragma unroll
        for (int q = 0; q < 18; q++) m[q] = fmaf(stw[q * 64 + k], lw, m[q]);
        tb = fmaf(stb[k], lw, tb);
    }
    float Wv = *Wp, Pv = *Pp, Nv = *Np;
    g_V[0][c] = m[0];
    g_V[1][c] = m[1];
    g_V[2][c] = m[6];
    g_V[3][c] = m[7];
    g_V[4][c] = Wv * m[8] + Pv * m[9] + Nv * m[10] + m[11];
    g_V[5][c] = m[12];
    g_V[6][c] = m[13];
    g_V[7][c] = Wv * m[14] + Pv * m[15] + Nv * m[16] + m[17];
    g_bias[c] = lin_b[c] + tb + Wv * m[2] + Pv * m[3] + Nv * m[4] + m[5];
}

#define VROWS 32
// Value = U @ V + bias; write Value; fused online-softmax stats on tmp = Value - pen
__global__ void k_value(float* __restrict__ Value) {
    __shared__ float4 sU2[VROWS][2];
    __shared__ float srw[VROWS], scl[VROWS];
    __shared__ float red_m[8], red_s[8];
    int t = threadIdx.x;
    int c0 = blockIdx.x * 1024 + t * 4;
    int i0 = blockIdx.y * VROWS;
    if (t < VROWS * 2)
        sU2[t >> 1][t & 1] = ((const float4*)g_U)[i0 * 2 + t];
    if (t < VROWS) { srw[t] = g_row[i0 + t]; scl[t] = g_colJ[i0 + t]; }
    __syncthreads();
    float4 V[8];
    #pragma unroll
    for (int q = 0; q < 8; q++) V[q] = *(const float4*)&g_V[q][c0];
    float4 bs = *(const float4*)&g_bias[c0];
    bool leftblk = (c0 < JN);
    float4 rowc = make_float4(0, 0, 0, 0), colc = make_float4(0, 0, 0, 0);
    if (leftblk) { rowc = *(const float4*)&g_row[c0]; colc = *(const float4*)&g_colJ[c0]; }
    float m = neg_inf(), s = 0.f;
    for (int r = 0; r < VROWS; r++) {
        int i = i0 + r;
        float4 u0 = sU2[r][0], u1 = sU2[r][1];
        float4 val = bs;
        val = f4fma(u0.x, V[0], val);
        val = f4fma(u0.y, V[1], val);
        val = f4fma(u0.z, V[2], val);
        val = f4fma(u0.w, V[3], val);
        val = f4fma(u1.x, V[4], val);
        val = f4fma(u1.y, V[5], val);
        val = f4fma(u1.z, V[6], val);
        val = f4fma(u1.w, V[7], val);
        __stcs((float4*)&Value[(size_t)i * CN + c0], val);
        float ri = srw[r], cli = scl[r];
        if (!leftblk) {
            float pen = ri * 10000.f;
            smupd(m, s, val.x - pen);
            smupd(m, s, val.y - pen);
            smupd(m, s, val.z - pen);
            smupd(m, s, val.w - pen);
        } else {
            float base = ri + cli;
            float px = ((c0 + 0) > i && base + rowc.x + colc.x == 0.f) ? 0.f : 10000.f;
            float py = ((c0 + 1) > i && base + rowc.y + colc.y == 0.f) ? 0.f : 10000.f;
            float pz = ((c0 + 2) > i && base + rowc.z + colc.z == 0.f) ? 0.f : 10000.f;
            float pw = ((c0 + 3) > i && base + rowc.w + colc.w == 0.f) ? 0.f : 10000.f;
            smupd(m, s, val.x - px);
            smupd(m, s, val.y - py);
            smupd(m, s, val.z - pz);
            smupd(m, s, val.w - pw);
        }
    }
    #pragma unroll
    for (int off = 16; off; off >>= 1) {
        float om = __shfl_xor_sync(0xffffffffu, m, off);
        float os = __shfl_xor_sync(0xffffffffu, s, off);
        smcomb(m, s, om, os);
    }
    if ((t & 31) == 0) { red_m[t >> 5] = m; red_s[t >> 5] = s; }
    __syncthreads();
    if (t == 0) {
        float M = red_m[0], S = red_s[0];
        for (int k = 1; k < 8; k++) smcomb(M, S, red_m[k], red_s[k]);
        int pid = blockIdx.y * gridDim.x + blockIdx.x;
        g_pm[pid] = M; g_ps[pid] = S;
    }
}

__global__ void k_gred() {
    __shared__ float rm[256], rs[256];
    int t = threadIdx.x;
    float m = neg_inf(), s = 0.f;
    for (int k = t; k < NPART; k += 256) smcomb(m, s, g_pm[k], g_ps[k]);
    rm[t] = m; rs[t] = s;
    __syncthreads();
    for (int w = 128; w; w >>= 1) {
        if (t < w) {
            float om = rm[t + w], os = rs[t + w];
            float mm = rm[t], ss = rs[t];
            smcomb(mm, ss, om, os);
            rm[t] = mm; rs[t] = ss;
        }
        __syncthreads();
    }
    if (t == 0) { g_gm = rm[0]; g_gs = rs[0]; }
}

// recompute Value (rank-8, cheaper than re-reading 128MB), write Poss
__global__ void k_poss(float* __restrict__ Poss) {
    __shared__ float4 sU2[VROWS][2];
    __shared__ float srw[VROWS], scl[VROWS];
    int t = threadIdx.x;
    int c0 = blockIdx.x * 1024 + t * 4;
    int i0 = blockIdx.y * VROWS;
    if (t < VROWS * 2)
        sU2[t >> 1][t & 1] = ((const float4*)g_U)[i0 * 2 + t];
    if (t < VROWS) { srw[t] = g_row[i0 + t]; scl[t] = g_colJ[i0 + t]; }
    __syncthreads();
    float4 V[8];
    #pragma unroll
    for (int q = 0; q < 8; q++) V[q] = *(const float4*)&g_V[q][c0];
    float4 bs = *(const float4*)&g_bias[c0];
    bool leftblk = (c0 < JN);
    float4 rowc = make_float4(0, 0, 0, 0), colc = make_float4(0, 0, 0, 0);
    if (leftblk) { rowc = *(const float4*)&g_row[c0]; colc = *(const float4*)&g_colJ[c0]; }
    float gm = g_gm;
    float rgs = 1.f / g_gs;
    for (int r = 0; r < VROWS; r++) {
        int i = i0 + r;
        float4 u0 = sU2[r][0], u1 = sU2[r][1];
        float4 val = bs;
        val = f4fma(u0.x, V[0], val);
        val = f4fma(u0.y, V[1], val);
        val = f4fma(u0.z, V[2], val);
        val = f4fma(u0.w, V[3], val);
        val = f4fma(u1.x, V[4], val);
        val = f4fma(u1.y, V[5], val);
        val = f4fma(u1.z, V[6], val);
        val = f4fma(u1.w, V[7], val);
        float ri = srw[r], cli = scl[r];
        float4 d;
        if (!leftblk) {
            float pen = ri * 10000.f + gm;
            d = make_float4(val.x - pen, val.y - pen, val.z - pen, val.w - pen);
        } else {
            float base = ri + cli;
            float px = ((c0 + 0) > i && base + rowc.x + colc.x == 0.f) ? 0.f : 10000.f;
            float py = ((c0 + 1) > i && base + rowc.y + colc.y == 0.f) ? 0.f : 10000.f;
            float pz = ((c0 + 2) > i && base + rowc.z + colc.z == 0.f) ? 0.f : 10000.f;
            float pw = ((c0 + 3) > i && base + rowc.w + colc.w == 0.f) ? 0.f : 10000.f;
            d = make_float4(val.x - px - gm, val.y - py - gm,
                            val.z - pz - gm, val.w - pw - gm);
        }
        float4 p;
        p.x = (d.x > -100.f) ? __expf(d.x) * rgs : 0.f;
        p.y = (d.y > -100.f) ? __expf(d.y) * rgs : 0.f;
        p.z = (d.z > -100.f) ? __expf(d.z) * rgs : 0.f;
        p.w = (d.w > -100.f) ? __expf(d.w) * rgs : 0.f;
        __stcs((float4*)&Poss[(size_t)i * CN + c0], p);
    }
}

// ---------------- launch ----------------
extern "C" void kernel_launch(void* const* d_in, const int* in_sizes, int n_in,
                              void* d_out, int out_size) {
    const float* h     = (const float*)d_in[0];
    const float* L     = (const float*)d_in[1];
    const float* Wp    = (const float*)d_in[2];
    const float* Pp    = (const float*)d_in[3];
    const float* Np    = (const float*)d_in[4];
    const float* G     = (const float*)d_in[5];
    const float* tag_w = (const float*)d_in[6];
    const float* tag_b = (const float*)d_in[7];
    const float* lin_w = (const float*)d_in[8];
    const float* lin_b = (const float*)d_in[9];
    float* Value = (float*)d_out;
    float* Poss  = Value + JC;

    k_init<<<16, 256>>>();
    k_rank<<<dim3(16, 16), 256>>>(h);
    k_scatter<<<16, 256>>>(h, L);
    k_sums<<<dim3(8, 128), 256>>>(G);
    k_fin1<<<16, 256>>>();
    k_prop<0><<<dim3(4, 32), 256>>>();
    k_fin2<<<16, 256>>>();
    k_prop<1><<<dim3(4, 32), 256>>>();
    k_fin3<<<16, 256>>>();
    k_vmat<<<32, 256>>>(tag_w, tag_b, lin_w, lin_b, Wp, Pp, Np);
    k_value<<<dim3(8, 128), 256>>>(Value);
    k_gred<<<1, 256>>>();
    k_poss<<<dim3(8, 128), 256>>>(Poss);
}